// round 14
// baseline (speedup 1.0000x reference)
#include <cuda_runtime.h>
#include <cuda_fp16.h>
#include <cstdint>

#define MAX_NODES 100000
#define MAX_EDGES 3200000
#define HID 64
#define CAP 128          // padded-CSR capacity per node (Poisson(32); max deg ~60)
#define MAX_SPILL 4096   // overflow list (expected empty)

// Scratch (__device__ globals; 16B aligned)
__device__ __align__(16) int    g_cnt[MAX_NODES];
__device__ __align__(16) int    g_srcs[MAX_NODES * CAP];  // padded CSR
__device__                int   g_nspill;
__device__ __align__(16) int    g_spill_d[MAX_SPILL];
__device__ __align__(16) int    g_spill_s[MAX_SPILL];
__device__ __align__(16) float  g_dinv[MAX_NODES];
__device__ __align__(16) __half g_h1[MAX_NODES * HID];   // x@W1 raw (unscaled), fp16
__device__ __align__(16) float  g_hid[MAX_NODES * HID];  // relu'd hidden (fp32)
__device__ __align__(16) __half g_h2[MAX_NODES * HID];   // (hid@W2)*dinv, fp16

// ---------------------------------------------------------------------------
// CSR construction (single pass, padded)
// ---------------------------------------------------------------------------
__global__ void zero_cnt_kernel(int* cnt, int* nspill, int N) {
    int i = blockIdx.x * blockDim.x + threadIdx.x;
    if (i < N) cnt[i] = 0;
    if (i == 0) *nspill = 0;
}

__global__ void hist_scatter_kernel(const int* __restrict__ src, const int* __restrict__ dst,
                                    int* cnt, int* __restrict__ srcs,
                                    int* nspill, int* spill_d, int* spill_s, int E) {
    int i = blockIdx.x * blockDim.x + threadIdx.x;
    if (i >= E) return;
    int s = src[i];
    int d = dst[i];
    int r = atomicAdd(&cnt[d], 1);
    if (r < CAP) {
        srcs[d * CAP + r] = s;
    } else {
        int k = atomicAdd(nspill, 1);
        if (k < MAX_SPILL) { spill_d[k] = d; spill_s[k] = s; }
    }
}

__global__ void dinv_kernel(const int* __restrict__ cnt, float* dinv, int N) {
    int i = blockIdx.x * blockDim.x + threadIdx.x;
    if (i < N) dinv[i] = rsqrtf((float)cnt[i] + 1.0f);  // +1 self-loop
}

// ---------------------------------------------------------------------------
// tf32 helpers
// ---------------------------------------------------------------------------
__device__ __forceinline__ unsigned f2tf32(float f) {
    unsigned u;
    asm("cvt.rna.tf32.f32 %0, %1;" : "=r"(u) : "f"(f));
    return u;
}

__device__ __forceinline__ void mma_tf32(float* c, const unsigned* a, const unsigned* b) {
    asm volatile(
        "mma.sync.aligned.m16n8k8.row.col.f32.tf32.tf32.f32 "
        "{%0,%1,%2,%3}, {%4,%5,%6,%7}, {%8,%9}, {%0,%1,%2,%3};"
        : "+f"(c[0]), "+f"(c[1]), "+f"(c[2]), "+f"(c[3])
        : "r"(a[0]), "r"(a[1]), "r"(a[2]), "r"(a[3]), "r"(b[0]), "r"(b[1]));
}

// ---------------------------------------------------------------------------
// tf32 GEMM, cp.async double-buffered, BM=64 (high occupancy):
// C = half( (A @ B) [* dinv[r] if SCALE] );  BN=64, BK=32; 8 warps (4m x 2n),
// warp tile 16x32.
// ---------------------------------------------------------------------------
#define ASTR 36
#define BSTR 72
#define ATILE (64 * ASTR)
#define BTILE (32 * BSTR)
#define GEMM_SMEM_BYTES (2 * (ATILE + BTILE) * 4)

template <int K, bool SCALE>
__launch_bounds__(256)
__global__ void gemm_tf32_kernel(const float* __restrict__ A, const float* __restrict__ Bm,
                                 const float* __restrict__ dinv, __half* __restrict__ C,
                                 int M) {
    extern __shared__ float smem[];
    float* As = smem;                 // [2][64][ASTR]
    float* Bs = smem + 2 * ATILE;     // [2][32][BSTR]

    constexpr int T = K / 32;
    const int tid = threadIdx.x;
    const int lane = tid & 31;
    const int warp = tid >> 5;
    const int wm = (warp & 3) * 16;   // warp row offset (4 warps cover 64)
    const int wn = (warp >> 2) * 32;  // warp col offset (2 warps cover 64)
    const int block_row = blockIdx.x * 64;
    const int g = lane >> 2;
    const int tg = lane & 3;

    float acc[4][4];
#pragma unroll
    for (int na = 0; na < 4; na++)
#pragma unroll
        for (int r = 0; r < 4; r++) acc[na][r] = 0.f;

    auto prefetch = [&](int t, int buf) {
        int k0 = t * 32;
        // A tile: 64x32 = 512 float4, 2 per thread
#pragma unroll
        for (int i = 0; i < 2; i++) {
            int idx = tid + i * 256;
            int r = idx >> 3;
            int c4 = (idx & 7) * 4;
            int grow = block_row + r;
            const float* sp = A + (size_t)(grow < M ? grow : 0) * K + k0 + c4;
            unsigned ds = (unsigned)__cvta_generic_to_shared(As + buf * ATILE + r * ASTR + c4);
            int sz = (grow < M) ? 16 : 0;
            asm volatile("cp.async.cg.shared.global [%0], [%1], 16, %2;"
                         :: "r"(ds), "l"(sp), "r"(sz));
        }
        // B tile: 32x64 = 512 float4, 2 per thread
#pragma unroll
        for (int i = 0; i < 2; i++) {
            int idx = tid + i * 256;
            int r = idx >> 4;
            int c4 = (idx & 15) * 4;
            const float* sp = Bm + (size_t)(k0 + r) * 64 + c4;
            unsigned ds = (unsigned)__cvta_generic_to_shared(Bs + buf * BTILE + r * BSTR + c4);
            asm volatile("cp.async.cg.shared.global [%0], [%1], 16;" :: "r"(ds), "l"(sp));
        }
        asm volatile("cp.async.commit_group;");
    };

    prefetch(0, 0);

    for (int t = 0; t < T; t++) {
        if (t + 1 < T) {
            prefetch(t + 1, (t + 1) & 1);
            asm volatile("cp.async.wait_group 1;");
        } else {
            asm volatile("cp.async.wait_group 0;");
        }
        __syncthreads();

        const float* At = As + (t & 1) * ATILE;
        const float* Bt = Bs + (t & 1) * BTILE;

#pragma unroll
        for (int ks = 0; ks < 4; ks++) {
            const int kb = ks * 8;
            unsigned a[4], b[4][2];
            int row = wm + g;
            a[0] = f2tf32(At[row * ASTR + kb + tg]);
            a[1] = f2tf32(At[(row + 8) * ASTR + kb + tg]);
            a[2] = f2tf32(At[row * ASTR + kb + tg + 4]);
            a[3] = f2tf32(At[(row + 8) * ASTR + kb + tg + 4]);
#pragma unroll
            for (int na = 0; na < 4; na++) {
                int col = wn + na * 8 + g;
                b[na][0] = f2tf32(Bt[(kb + tg) * BSTR + col]);
                b[na][1] = f2tf32(Bt[(kb + tg + 4) * BSTR + col]);
            }
#pragma unroll
            for (int na = 0; na < 4; na++) mma_tf32(acc[na], a, b[na]);
        }
        __syncthreads();
    }

    int row_lo = block_row + wm + g;
    int row_hi = row_lo + 8;
    float s_lo = 1.f, s_hi = 1.f;
    if (SCALE) {
        s_lo = (row_lo < M) ? dinv[row_lo] : 0.f;
        s_hi = (row_hi < M) ? dinv[row_hi] : 0.f;
    }
#pragma unroll
    for (int na = 0; na < 4; na++) {
        int col = wn + na * 8 + 2 * tg;
        if (row_lo < M) {
            __half2 h = __floats2half2_rn(acc[na][0] * s_lo, acc[na][1] * s_lo);
            *reinterpret_cast<__half2*>(&C[(size_t)row_lo * 64 + col]) = h;
        }
        if (row_hi < M) {
            __half2 h = __floats2half2_rn(acc[na][2] * s_hi, acc[na][3] * s_hi);
            *reinterpret_cast<__half2*>(&C[(size_t)row_hi * 64 + col]) = h;
        }
    }
}

// ---------------------------------------------------------------------------
// fp16 helpers
// ---------------------------------------------------------------------------
__device__ __forceinline__ void acc_half4(float4& acc, uint2 u) {
    __half2 h0 = *reinterpret_cast<const __half2*>(&u.x);
    __half2 h1 = *reinterpret_cast<const __half2*>(&u.y);
    float2 f0 = __half22float2(h0);
    float2 f1 = __half22float2(h1);
    acc.x += f0.x; acc.y += f0.y; acc.z += f1.x; acc.w += f1.y;
}

__device__ __forceinline__ void acc_half4_s(float4& acc, uint2 u, float s) {
    __half2 h0 = *reinterpret_cast<const __half2*>(&u.x);
    __half2 h1 = *reinterpret_cast<const __half2*>(&u.y);
    float2 f0 = __half22float2(h0);
    float2 f1 = __half22float2(h1);
    acc.x = fmaf(f0.x, s, acc.x); acc.y = fmaf(f0.y, s, acc.y);
    acc.z = fmaf(f1.x, s, acc.z); acc.w = fmaf(f1.y, s, acc.w);
}

// ---------------------------------------------------------------------------
// Gather-reduce (fp16 table, padded CSR).
// SRCSCALE: table rows are raw; multiply each gathered row by dinv[src].
// out[d] = dinv[d]*(w_self*h[d] + sum w_s*h[src]) + bias  (w = dinv[...] or 1)
// ---------------------------------------------------------------------------
template <bool RELU, bool SRCSCALE>
__global__ void gather_kernel(const uint2* __restrict__ hs, const int* __restrict__ cnt,
                              const int* __restrict__ srcs, const float* __restrict__ dinv,
                              const float* __restrict__ bias,
                              const int* __restrict__ nspill, const int* __restrict__ spill_d,
                              const int* __restrict__ spill_s,
                              float4* __restrict__ out, int N) {
    int i = blockIdx.x * blockDim.x + threadIdx.x;
    if (i >= N * 16) return;
    int node = i >> 4;
    int lane = i & 15;

    float dd = dinv[node];
    float4 acc = make_float4(0.f, 0.f, 0.f, 0.f);
    // self-loop term
    if (SRCSCALE) acc_half4_s(acc, hs[(size_t)node * 16 + lane], dd);
    else          acc_half4(acc, hs[(size_t)node * 16 + lane]);

    const int c = cnt[node];
    int e = node * CAP;
    const int end = e + min(c, CAP);

    for (; e + 4 <= end; e += 4) {
        int s0 = srcs[e], s1 = srcs[e + 1], s2 = srcs[e + 2], s3 = srcs[e + 3];
        uint2 v0 = hs[(size_t)s0 * 16 + lane];
        uint2 v1 = hs[(size_t)s1 * 16 + lane];
        uint2 v2 = hs[(size_t)s2 * 16 + lane];
        uint2 v3 = hs[(size_t)s3 * 16 + lane];
        if (SRCSCALE) {
            acc_half4_s(acc, v0, dinv[s0]); acc_half4_s(acc, v1, dinv[s1]);
            acc_half4_s(acc, v2, dinv[s2]); acc_half4_s(acc, v3, dinv[s3]);
        } else {
            acc_half4(acc, v0); acc_half4(acc, v1);
            acc_half4(acc, v2); acc_half4(acc, v3);
        }
    }
    for (; e < end; e++) {
        int s = srcs[e];
        if (SRCSCALE) acc_half4_s(acc, hs[(size_t)s * 16 + lane], dinv[s]);
        else          acc_half4(acc, hs[(size_t)s * 16 + lane]);
    }

    if (c > CAP) {  // overflow fixup (empty in practice)
        int ns = min(*nspill, MAX_SPILL);
        for (int j = 0; j < ns; j++)
            if (spill_d[j] == node) {
                int s = spill_s[j];
                if (SRCSCALE) acc_half4_s(acc, hs[(size_t)s * 16 + lane], dinv[s]);
                else          acc_half4(acc, hs[(size_t)s * 16 + lane]);
            }
    }

    float4 bv = reinterpret_cast<const float4*>(bias)[lane];
    float r0 = fmaf(acc.x, dd, bv.x);
    float r1 = fmaf(acc.y, dd, bv.y);
    float r2 = fmaf(acc.z, dd, bv.z);
    float r3 = fmaf(acc.w, dd, bv.w);
    if (RELU) {
        r0 = fmaxf(r0, 0.f); r1 = fmaxf(r1, 0.f);
        r2 = fmaxf(r2, 0.f); r3 = fmaxf(r3, 0.f);
    }
    out[(size_t)node * 16 + lane] = make_float4(r0, r1, r2, r3);
}

// ---------------------------------------------------------------------------
// launch: graph fork — CSR build (side stream) overlaps GEMM1 raw (main)
// ---------------------------------------------------------------------------
extern "C" void kernel_launch(void* const* d_in, const int* in_sizes, int n_in,
                              void* d_out, int out_size) {
    const float* x = (const float*)d_in[0];
    const int* edge_index = (const int*)d_in[1];
    const float* W1 = (const float*)d_in[2];
    const float* b1 = (const float*)d_in[3];
    const float* W2 = (const float*)d_in[4];
    const float* b2 = (const float*)d_in[5];
    float* out = (float*)d_out;

    const int IN_CH = 256;
    const int N = in_sizes[0] / IN_CH;  // 100000
    const int E = in_sizes[1] / 2;      // 3200000
    const int* src = edge_index;
    const int* dst = edge_index + E;

    int *cnt, *srcs, *nspill, *spill_d, *spill_s;
    float *dinv, *hid;
    __half *h1, *h2;
    cudaGetSymbolAddress((void**)&cnt, g_cnt);
    cudaGetSymbolAddress((void**)&srcs, g_srcs);
    cudaGetSymbolAddress((void**)&nspill, g_nspill);
    cudaGetSymbolAddress((void**)&spill_d, g_spill_d);
    cudaGetSymbolAddress((void**)&spill_s, g_spill_s);
    cudaGetSymbolAddress((void**)&dinv, g_dinv);
    cudaGetSymbolAddress((void**)&h1, g_h1);
    cudaGetSymbolAddress((void**)&hid, g_hid);
    cudaGetSymbolAddress((void**)&h2, g_h2);

    static cudaStream_t s_side = nullptr;
    static cudaEvent_t evA = nullptr, evB = nullptr;
    if (s_side == nullptr) {
        cudaFuncSetAttribute((const void*)gemm_tf32_kernel<256, false>,
                             cudaFuncAttributeMaxDynamicSharedMemorySize, GEMM_SMEM_BYTES);
        cudaFuncSetAttribute((const void*)gemm_tf32_kernel<64, true>,
                             cudaFuncAttributeMaxDynamicSharedMemorySize, GEMM_SMEM_BYTES);
        cudaStreamCreateWithFlags(&s_side, cudaStreamNonBlocking);
        cudaEventCreateWithFlags(&evA, cudaEventDisableTiming);
        cudaEventCreateWithFlags(&evB, cudaEventDisableTiming);
    }

    const int T = 256;
    int nBlkN = (N + T - 1) / T;
    int nBlkE = (E + T - 1) / T;
    int nBlkG = (N + 63) / 64;
    int nBlkGa = (N * 16 + T - 1) / T;

    // main stream: zero counters, then fork
    zero_cnt_kernel<<<nBlkN, T>>>(cnt, nspill, N);
    cudaEventRecord(evA, 0);

    // side branch: CSR build + dinv
    cudaStreamWaitEvent(s_side, evA, 0);
    hist_scatter_kernel<<<nBlkE, T, 0, s_side>>>(src, dst, cnt, srcs,
                                                 nspill, spill_d, spill_s, E);
    dinv_kernel<<<nBlkN, T, 0, s_side>>>(cnt, dinv, N);
    cudaEventRecord(evB, s_side);

    // main branch: GEMM1 raw (no dinv dependency) — overlaps with side
    gemm_tf32_kernel<256, false><<<nBlkG, T, GEMM_SMEM_BYTES>>>(x, W1, dinv, h1, N);

    // join; gather1 applies dinv[src] on the fly (+b1, relu) -> hid fp32
    cudaStreamWaitEvent(0, evB, 0);
    gather_kernel<true, true><<<nBlkGa, T>>>((const uint2*)h1, cnt, srcs, dinv, b1,
                                             nspill, spill_d, spill_s, (float4*)hid, N);

    // layer 2 GEMM (scaled) -> h2 fp16
    gemm_tf32_kernel<64, true><<<nBlkG, T, GEMM_SMEM_BYTES>>>(hid, W2, dinv, h2, N);

    // final aggregation (+b2) -> fp32 out
    gather_kernel<false, false><<<nBlkGa, T>>>((const uint2*)h2, cnt, srcs, dinv, b2,
                                               nspill, spill_d, spill_s, (float4*)out, N);
}

// round 16
// speedup vs baseline: 1.0649x; 1.0649x over previous
#include <cuda_runtime.h>
#include <cuda_fp16.h>
#include <cstdint>

#define MAX_NODES 100000
#define MAX_EDGES 3200000
#define HID 64
#define CAP 64           // padded-CSR capacity (Poisson(32): P(deg>64)~1e-7; spill backstop)
#define MAX_SPILL 4096   // overflow list (expected empty)

// Scratch (__device__ globals; 16B aligned)
__device__ __align__(16) int    g_cnt[MAX_NODES];
__device__ __align__(16) int    g_srcs[MAX_NODES * CAP];  // padded CSR, 25.6 MB (L2-resident)
__device__                int   g_nspill;
__device__ __align__(16) int    g_spill_d[MAX_SPILL];
__device__ __align__(16) int    g_spill_s[MAX_SPILL];
__device__ __align__(16) float  g_dinv[MAX_NODES];
__device__ __align__(16) __half g_h1[MAX_NODES * HID];   // x@W1 raw, then *dinv in place
__device__ __align__(16) float  g_hid[MAX_NODES * HID];  // relu'd hidden (fp32)
__device__ __align__(16) __half g_h2[MAX_NODES * HID];   // (hid@W2)*dinv, fp16

// ---------------------------------------------------------------------------
// CSR construction (single pass, padded)
// ---------------------------------------------------------------------------
__global__ void zero_cnt_kernel(int* cnt, int* nspill, int N) {
    int i = blockIdx.x * blockDim.x + threadIdx.x;
    if (i < N) cnt[i] = 0;
    if (i == 0) *nspill = 0;
}

__global__ void hist_scatter_kernel(const int* __restrict__ src, const int* __restrict__ dst,
                                    int* cnt, int* __restrict__ srcs,
                                    int* nspill, int* spill_d, int* spill_s, int E) {
    int i = blockIdx.x * blockDim.x + threadIdx.x;
    if (i >= E) return;
    int s = src[i];
    int d = dst[i];
    int r = atomicAdd(&cnt[d], 1);
    if (r < CAP) {
        srcs[d * CAP + r] = s;
    } else {
        int k = atomicAdd(nspill, 1);
        if (k < MAX_SPILL) { spill_d[k] = d; spill_s[k] = s; }
    }
}

__global__ void dinv_kernel(const int* __restrict__ cnt, float* dinv, int N) {
    int i = blockIdx.x * blockDim.x + threadIdx.x;
    if (i < N) dinv[i] = rsqrtf((float)cnt[i] + 1.0f);  // +1 self-loop
}

// h1[i] *= dinv[node]  (fp16 in place; coalesced, 4 halves per thread)
__global__ void scale_h1_kernel(uint2* __restrict__ h1, const float* __restrict__ dinv, int N) {
    int i = blockIdx.x * blockDim.x + threadIdx.x;
    if (i >= N * 16) return;
    float dd = dinv[i >> 4];
    uint2 u = h1[i];
    __half2 a = *reinterpret_cast<__half2*>(&u.x);
    __half2 b = *reinterpret_cast<__half2*>(&u.y);
    float2 fa = __half22float2(a);
    float2 fb = __half22float2(b);
    __half2 ra = __floats2half2_rn(fa.x * dd, fa.y * dd);
    __half2 rb = __floats2half2_rn(fb.x * dd, fb.y * dd);
    u.x = *reinterpret_cast<unsigned*>(&ra);
    u.y = *reinterpret_cast<unsigned*>(&rb);
    h1[i] = u;
}

// ---------------------------------------------------------------------------
// tf32 helpers — RNA rounding is REQUIRED (R15: truncation -> rel_err 1.4e-3)
// ---------------------------------------------------------------------------
__device__ __forceinline__ unsigned f2tf32(float f) {
    unsigned u;
    asm("cvt.rna.tf32.f32 %0, %1;" : "=r"(u) : "f"(f));
    return u;
}

__device__ __forceinline__ void mma_tf32(float* c, const unsigned* a, const unsigned* b) {
    asm volatile(
        "mma.sync.aligned.m16n8k8.row.col.f32.tf32.tf32.f32 "
        "{%0,%1,%2,%3}, {%4,%5,%6,%7}, {%8,%9}, {%0,%1,%2,%3};"
        : "+f"(c[0]), "+f"(c[1]), "+f"(c[2]), "+f"(c[3])
        : "r"(a[0]), "r"(a[1]), "r"(a[2]), "r"(a[3]), "r"(b[0]), "r"(b[1]));
}

// ---------------------------------------------------------------------------
// tf32 GEMM, cp.async double-buffered, BM=128:
// C = half( (A @ B) [* dinv[r] if SCALE] );  BN=64, BK=32; 8 warps.
// ---------------------------------------------------------------------------
#define ASTR 36
#define BSTR 72
#define ATILE (128 * ASTR)
#define BTILE (32 * BSTR)
#define GEMM_SMEM_BYTES (2 * (ATILE + BTILE) * 4)

template <int K, bool SCALE>
__launch_bounds__(256)
__global__ void gemm_tf32_kernel(const float* __restrict__ A, const float* __restrict__ Bm,
                                 const float* __restrict__ dinv, __half* __restrict__ C,
                                 int M) {
    extern __shared__ float smem[];
    float* As = smem;
    float* Bs = smem + 2 * ATILE;

    constexpr int T = K / 32;
    const int tid = threadIdx.x;
    const int lane = tid & 31;
    const int warp = tid >> 5;
    const int wm = (warp & 3) * 32;
    const int wn = (warp >> 2) * 32;
    const int block_row = blockIdx.x * 128;
    const int g = lane >> 2;
    const int tg = lane & 3;

    float acc[2][4][4];
#pragma unroll
    for (int mi = 0; mi < 2; mi++)
#pragma unroll
        for (int na = 0; na < 4; na++)
#pragma unroll
            for (int r = 0; r < 4; r++) acc[mi][na][r] = 0.f;

    auto prefetch = [&](int t, int buf) {
        int k0 = t * 32;
#pragma unroll
        for (int i = 0; i < 4; i++) {
            int idx = tid + i * 256;
            int r = idx >> 3;
            int c4 = (idx & 7) * 4;
            int grow = block_row + r;
            const float* sp = A + (size_t)(grow < M ? grow : 0) * K + k0 + c4;
            unsigned ds = (unsigned)__cvta_generic_to_shared(As + buf * ATILE + r * ASTR + c4);
            int sz = (grow < M) ? 16 : 0;
            asm volatile("cp.async.cg.shared.global [%0], [%1], 16, %2;"
                         :: "r"(ds), "l"(sp), "r"(sz));
        }
#pragma unroll
        for (int i = 0; i < 2; i++) {
            int idx = tid + i * 256;
            int r = idx >> 4;
            int c4 = (idx & 15) * 4;
            const float* sp = Bm + (size_t)(k0 + r) * 64 + c4;
            unsigned ds = (unsigned)__cvta_generic_to_shared(Bs + buf * BTILE + r * BSTR + c4);
            asm volatile("cp.async.cg.shared.global [%0], [%1], 16;" :: "r"(ds), "l"(sp));
        }
        asm volatile("cp.async.commit_group;");
    };

    prefetch(0, 0);

    for (int t = 0; t < T; t++) {
        if (t + 1 < T) {
            prefetch(t + 1, (t + 1) & 1);
            asm volatile("cp.async.wait_group 1;");
        } else {
            asm volatile("cp.async.wait_group 0;");
        }
        __syncthreads();

        const float* At = As + (t & 1) * ATILE;
        const float* Bt = Bs + (t & 1) * BTILE;

#pragma unroll
        for (int ks = 0; ks < 4; ks++) {
            const int kb = ks * 8;
            unsigned a[2][4], b[4][2];
#pragma unroll
            for (int mi = 0; mi < 2; mi++) {
                int row = wm + mi * 16 + g;
                a[mi][0] = f2tf32(At[row * ASTR + kb + tg]);
                a[mi][1] = f2tf32(At[(row + 8) * ASTR + kb + tg]);
                a[mi][2] = f2tf32(At[row * ASTR + kb + tg + 4]);
                a[mi][3] = f2tf32(At[(row + 8) * ASTR + kb + tg + 4]);
            }
#pragma unroll
            for (int na = 0; na < 4; na++) {
                int col = wn + na * 8 + g;
                b[na][0] = f2tf32(Bt[(kb + tg) * BSTR + col]);
                b[na][1] = f2tf32(Bt[(kb + tg + 4) * BSTR + col]);
            }
#pragma unroll
            for (int mi = 0; mi < 2; mi++)
#pragma unroll
                for (int na = 0; na < 4; na++) mma_tf32(acc[mi][na], a[mi], b[na]);
        }
        __syncthreads();
    }

#pragma unroll
    for (int mi = 0; mi < 2; mi++) {
        int row_lo = block_row + wm + mi * 16 + g;
        int row_hi = row_lo + 8;
        float s_lo = 1.f, s_hi = 1.f;
        if (SCALE) {
            s_lo = (row_lo < M) ? dinv[row_lo] : 0.f;
            s_hi = (row_hi < M) ? dinv[row_hi] : 0.f;
        }
#pragma unroll
        for (int na = 0; na < 4; na++) {
            int col = wn + na * 8 + 2 * tg;
            if (row_lo < M) {
                __half2 h = __floats2half2_rn(acc[mi][na][0] * s_lo, acc[mi][na][1] * s_lo);
                *reinterpret_cast<__half2*>(&C[(size_t)row_lo * 64 + col]) = h;
            }
            if (row_hi < M) {
                __half2 h = __floats2half2_rn(acc[mi][na][2] * s_hi, acc[mi][na][3] * s_hi);
                *reinterpret_cast<__half2*>(&C[(size_t)row_hi * 64 + col]) = h;
            }
        }
    }
}

// ---------------------------------------------------------------------------
// Gather-reduce (fp16 table, padded CSR)
// ---------------------------------------------------------------------------
__device__ __forceinline__ void acc_half4(float4& acc, uint2 u) {
    __half2 h0 = *reinterpret_cast<const __half2*>(&u.x);
    __half2 h1 = *reinterpret_cast<const __half2*>(&u.y);
    float2 f0 = __half22float2(h0);
    float2 f1 = __half22float2(h1);
    acc.x += f0.x; acc.y += f0.y; acc.z += f1.x; acc.w += f1.y;
}

template <bool RELU>
__global__ void gather_kernel(const uint2* __restrict__ hs, const int* __restrict__ cnt,
                              const int* __restrict__ srcs, const float* __restrict__ dinv,
                              const float* __restrict__ bias,
                              const int* __restrict__ nspill, const int* __restrict__ spill_d,
                              const int* __restrict__ spill_s,
                              float4* __restrict__ out, int N) {
    int i = blockIdx.x * blockDim.x + threadIdx.x;
    if (i >= N * 16) return;
    int node = i >> 4;
    int lane = i & 15;

    float4 acc = make_float4(0.f, 0.f, 0.f, 0.f);
    acc_half4(acc, hs[(size_t)node * 16 + lane]);  // self-loop term
    const int c = cnt[node];
    int e = node * CAP;
    const int end = e + min(c, CAP);

    for (; e + 4 <= end; e += 4) {
        int s0 = srcs[e], s1 = srcs[e + 1], s2 = srcs[e + 2], s3 = srcs[e + 3];
        uint2 v0 = hs[(size_t)s0 * 16 + lane];
        uint2 v1 = hs[(size_t)s1 * 16 + lane];
        uint2 v2 = hs[(size_t)s2 * 16 + lane];
        uint2 v3 = hs[(size_t)s3 * 16 + lane];
        acc_half4(acc, v0); acc_half4(acc, v1);
        acc_half4(acc, v2); acc_half4(acc, v3);
    }
    for (; e < end; e++) acc_half4(acc, hs[(size_t)srcs[e] * 16 + lane]);

    if (c > CAP) {  // overflow fixup (empty in practice)
        int ns = min(*nspill, MAX_SPILL);
        for (int j = 0; j < ns; j++)
            if (spill_d[j] == node) acc_half4(acc, hs[(size_t)spill_s[j] * 16 + lane]);
    }

    float dd = dinv[node];
    float4 bv = reinterpret_cast<const float4*>(bias)[lane];
    float r0 = fmaf(acc.x, dd, bv.x);
    float r1 = fmaf(acc.y, dd, bv.y);
    float r2 = fmaf(acc.z, dd, bv.z);
    float r3 = fmaf(acc.w, dd, bv.w);
    if (RELU) {
        r0 = fmaxf(r0, 0.f); r1 = fmaxf(r1, 0.f);
        r2 = fmaxf(r2, 0.f); r3 = fmaxf(r3, 0.f);
    }
    out[(size_t)node * 16 + lane] = make_float4(r0, r1, r2, r3);
}

// ---------------------------------------------------------------------------
// launch: graph fork — CSR build (side stream) overlaps GEMM1 raw (main)
// ---------------------------------------------------------------------------
extern "C" void kernel_launch(void* const* d_in, const int* in_sizes, int n_in,
                              void* d_out, int out_size) {
    const float* x = (const float*)d_in[0];
    const int* edge_index = (const int*)d_in[1];
    const float* W1 = (const float*)d_in[2];
    const float* b1 = (const float*)d_in[3];
    const float* W2 = (const float*)d_in[4];
    const float* b2 = (const float*)d_in[5];
    float* out = (float*)d_out;

    const int IN_CH = 256;
    const int N = in_sizes[0] / IN_CH;  // 100000
    const int E = in_sizes[1] / 2;      // 3200000
    const int* src = edge_index;
    const int* dst = edge_index + E;

    int *cnt, *srcs, *nspill, *spill_d, *spill_s;
    float *dinv, *hid;
    __half *h1, *h2;
    cudaGetSymbolAddress((void**)&cnt, g_cnt);
    cudaGetSymbolAddress((void**)&srcs, g_srcs);
    cudaGetSymbolAddress((void**)&nspill, g_nspill);
    cudaGetSymbolAddress((void**)&spill_d, g_spill_d);
    cudaGetSymbolAddress((void**)&spill_s, g_spill_s);
    cudaGetSymbolAddress((void**)&dinv, g_dinv);
    cudaGetSymbolAddress((void**)&h1, g_h1);
    cudaGetSymbolAddress((void**)&hid, g_hid);
    cudaGetSymbolAddress((void**)&h2, g_h2);

    static cudaStream_t s_side = nullptr;
    static cudaEvent_t evA = nullptr, evB = nullptr;
    if (s_side == nullptr) {
        cudaFuncSetAttribute((const void*)gemm_tf32_kernel<256, false>,
                             cudaFuncAttributeMaxDynamicSharedMemorySize, GEMM_SMEM_BYTES);
        cudaFuncSetAttribute((const void*)gemm_tf32_kernel<64, true>,
                             cudaFuncAttributeMaxDynamicSharedMemorySize, GEMM_SMEM_BYTES);
        cudaStreamCreateWithFlags(&s_side, cudaStreamNonBlocking);
        cudaEventCreateWithFlags(&evA, cudaEventDisableTiming);
        cudaEventCreateWithFlags(&evB, cudaEventDisableTiming);
    }

    const int T = 256;
    int nBlkN = (N + T - 1) / T;
    int nBlkE = (E + T - 1) / T;
    int nBlkG = (N + 127) / 128;
    int nBlkGa = (N * 16 + T - 1) / T;

    // main stream: zero counters, then fork
    zero_cnt_kernel<<<nBlkN, T>>>(cnt, nspill, N);
    cudaEventRecord(evA, 0);

    // side branch: CSR build + dinv
    cudaStreamWaitEvent(s_side, evA, 0);
    hist_scatter_kernel<<<nBlkE, T, 0, s_side>>>(src, dst, cnt, srcs,
                                                 nspill, spill_d, spill_s, E);
    dinv_kernel<<<nBlkN, T, 0, s_side>>>(cnt, dinv, N);
    cudaEventRecord(evB, s_side);

    // main branch: GEMM1 raw (no dinv dependency) — overlaps with side
    gemm_tf32_kernel<256, false><<<nBlkG, T, GEMM_SMEM_BYTES>>>(x, W1, dinv, h1, N);

    // join, then scale h1 by dinv in place
    cudaStreamWaitEvent(0, evB, 0);
    scale_h1_kernel<<<nBlkGa, T>>>((uint2*)h1, dinv, N);

    // layer 1 aggregation (+b1, relu) -> hid fp32
    gather_kernel<true><<<nBlkGa, T>>>((const uint2*)h1, cnt, srcs, dinv, b1,
                                       nspill, spill_d, spill_s, (float4*)hid, N);

    // layer 2 GEMM (scaled) -> h2 fp16
    gemm_tf32_kernel<64, true><<<nBlkG, T, GEMM_SMEM_BYTES>>>(hid, W2, dinv, h2, N);

    // final aggregation (+b2) -> fp32 out
    gather_kernel<false><<<nBlkGa, T>>>((const uint2*)h2, cnt, srcs, dinv, b2,
                                        nspill, spill_d, spill_s, (float4*)out, N);
}

// round 17
// speedup vs baseline: 1.0684x; 1.0033x over previous
#include <cuda_runtime.h>
#include <cuda_fp16.h>
#include <cstdint>

#define MAX_NODES 100000
#define MAX_EDGES 3200000
#define HID 64
#define CAP 64           // padded-CSR capacity (Poisson(32): P(deg>64)~1e-7; spill backstop)
#define MAX_SPILL 4096   // overflow list (expected empty)

// Scratch (__device__ globals; 16B aligned)
__device__ __align__(16) int    g_cnt[MAX_NODES];
__device__ __align__(16) int    g_srcs[MAX_NODES * CAP];  // padded CSR, 25.6 MB
__device__                int   g_nspill;
__device__ __align__(16) int    g_spill_d[MAX_SPILL];
__device__ __align__(16) int    g_spill_s[MAX_SPILL];
__device__ __align__(16) float  g_dinv[MAX_NODES];
__device__ __align__(16) __half g_h1[MAX_NODES * HID];   // x@W1 raw, then *dinv in place
__device__ __align__(16) float  g_hid[MAX_NODES * HID];  // relu'd hidden (fp32)
__device__ __align__(16) __half g_h2[MAX_NODES * HID];   // (hid@W2)*dinv, fp16

// ---------------------------------------------------------------------------
// CSR construction (single pass, padded)
// ---------------------------------------------------------------------------
__global__ void zero_cnt_kernel(int* cnt, int* nspill, int N) {
    int i = blockIdx.x * blockDim.x + threadIdx.x;
    if (i < N) cnt[i] = 0;
    if (i == 0) *nspill = 0;
}

__global__ void hist_scatter_kernel(const int* __restrict__ src, const int* __restrict__ dst,
                                    int* cnt, int* __restrict__ srcs,
                                    int* nspill, int* spill_d, int* spill_s, int E) {
    int i = blockIdx.x * blockDim.x + threadIdx.x;
    if (i >= E) return;
    int s = src[i];
    int d = dst[i];
    int r = atomicAdd(&cnt[d], 1);
    if (r < CAP) {
        srcs[d * CAP + r] = s;
    } else {
        int k = atomicAdd(nspill, 1);
        if (k < MAX_SPILL) { spill_d[k] = d; spill_s[k] = s; }
    }
}

__global__ void dinv_kernel(const int* __restrict__ cnt, float* dinv, int N) {
    int i = blockIdx.x * blockDim.x + threadIdx.x;
    if (i < N) dinv[i] = rsqrtf((float)cnt[i] + 1.0f);  // +1 self-loop
}

// h1[i] *= dinv[node]  (fp16 in place; coalesced)
__global__ void scale_h1_kernel(uint2* __restrict__ h1, const float* __restrict__ dinv, int N) {
    int i = blockIdx.x * blockDim.x + threadIdx.x;
    if (i >= N * 16) return;
    float dd = dinv[i >> 4];
    uint2 u = h1[i];
    __half2 a = *reinterpret_cast<__half2*>(&u.x);
    __half2 b = *reinterpret_cast<__half2*>(&u.y);
    float2 fa = __half22float2(a);
    float2 fb = __half22float2(b);
    __half2 ra = __floats2half2_rn(fa.x * dd, fa.y * dd);
    __half2 rb = __floats2half2_rn(fb.x * dd, fb.y * dd);
    u.x = *reinterpret_cast<unsigned*>(&ra);
    u.y = *reinterpret_cast<unsigned*>(&rb);
    h1[i] = u;
}

// ---------------------------------------------------------------------------
// tf32 helpers — RNA rounding REQUIRED (R15: truncation -> rel_err 1.4e-3)
// ---------------------------------------------------------------------------
__device__ __forceinline__ unsigned f2tf32(float f) {
    unsigned u;
    asm("cvt.rna.tf32.f32 %0, %1;" : "=r"(u) : "f"(f));
    return u;
}

__device__ __forceinline__ void mma_tf32(float* c, const unsigned* a, const unsigned* b) {
    asm volatile(
        "mma.sync.aligned.m16n8k8.row.col.f32.tf32.tf32.f32 "
        "{%0,%1,%2,%3}, {%4,%5,%6,%7}, {%8,%9}, {%0,%1,%2,%3};"
        : "+f"(c[0]), "+f"(c[1]), "+f"(c[2]), "+f"(c[3])
        : "r"(a[0]), "r"(a[1]), "r"(a[2]), "r"(a[3]), "r"(b[0]), "r"(b[1]));
}

// ---------------------------------------------------------------------------
// tf32 GEMM, cp.async double-buffered, BM=128, forced 4 CTAs/SM:
// C = half( (A @ B) [* dinv[r] if SCALE] );  BN=64, BK=32; 8 warps.
// ---------------------------------------------------------------------------
#define ASTR 36
#define BSTR 72
#define ATILE (128 * ASTR)
#define BTILE (32 * BSTR)
#define GEMM_SMEM_BYTES (2 * (ATILE + BTILE) * 4)

template <int K, bool SCALE>
__launch_bounds__(256, 4)
__global__ void gemm_tf32_kernel(const float* __restrict__ A, const float* __restrict__ Bm,
                                 const float* __restrict__ dinv, __half* __restrict__ C,
                                 int M) {
    extern __shared__ float smem[];
    float* As = smem;
    float* Bs = smem + 2 * ATILE;

    constexpr int T = K / 32;
    const int tid = threadIdx.x;
    const int lane = tid & 31;
    const int warp = tid >> 5;
    const int wm = (warp & 3) * 32;
    const int wn = (warp >> 2) * 32;
    const int block_row = blockIdx.x * 128;
    const int g = lane >> 2;
    const int tg = lane & 3;

    float acc[2][4][4];
#pragma unroll
    for (int mi = 0; mi < 2; mi++)
#pragma unroll
        for (int na = 0; na < 4; na++)
#pragma unroll
            for (int r = 0; r < 4; r++) acc[mi][na][r] = 0.f;

    auto prefetch = [&](int t, int buf) {
        int k0 = t * 32;
#pragma unroll
        for (int i = 0; i < 4; i++) {
            int idx = tid + i * 256;
            int r = idx >> 3;
            int c4 = (idx & 7) * 4;
            int grow = block_row + r;
            const float* sp = A + (size_t)(grow < M ? grow : 0) * K + k0 + c4;
            unsigned ds = (unsigned)__cvta_generic_to_shared(As + buf * ATILE + r * ASTR + c4);
            int sz = (grow < M) ? 16 : 0;
            asm volatile("cp.async.cg.shared.global [%0], [%1], 16, %2;"
                         :: "r"(ds), "l"(sp), "r"(sz));
        }
#pragma unroll
        for (int i = 0; i < 2; i++) {
            int idx = tid + i * 256;
            int r = idx >> 4;
            int c4 = (idx & 15) * 4;
            const float* sp = Bm + (size_t)(k0 + r) * 64 + c4;
            unsigned ds = (unsigned)__cvta_generic_to_shared(Bs + buf * BTILE + r * BSTR + c4);
            asm volatile("cp.async.cg.shared.global [%0], [%1], 16;" :: "r"(ds), "l"(sp));
        }
        asm volatile("cp.async.commit_group;");
    };

    prefetch(0, 0);

    for (int t = 0; t < T; t++) {
        if (t + 1 < T) {
            prefetch(t + 1, (t + 1) & 1);
            asm volatile("cp.async.wait_group 1;");
        } else {
            asm volatile("cp.async.wait_group 0;");
        }
        __syncthreads();

        const float* At = As + (t & 1) * ATILE;
        const float* Bt = Bs + (t & 1) * BTILE;

#pragma unroll
        for (int ks = 0; ks < 4; ks++) {
            const int kb = ks * 8;
            unsigned a[2][4], b[4][2];
#pragma unroll
            for (int mi = 0; mi < 2; mi++) {
                int row = wm + mi * 16 + g;
                a[mi][0] = f2tf32(At[row * ASTR + kb + tg]);
                a[mi][1] = f2tf32(At[(row + 8) * ASTR + kb + tg]);
                a[mi][2] = f2tf32(At[row * ASTR + kb + tg + 4]);
                a[mi][3] = f2tf32(At[(row + 8) * ASTR + kb + tg + 4]);
            }
#pragma unroll
            for (int na = 0; na < 4; na++) {
                int col = wn + na * 8 + g;
                b[na][0] = f2tf32(Bt[(kb + tg) * BSTR + col]);
                b[na][1] = f2tf32(Bt[(kb + tg + 4) * BSTR + col]);
            }
#pragma unroll
            for (int mi = 0; mi < 2; mi++)
#pragma unroll
                for (int na = 0; na < 4; na++) mma_tf32(acc[mi][na], a[mi], b[na]);
        }
        __syncthreads();
    }

#pragma unroll
    for (int mi = 0; mi < 2; mi++) {
        int row_lo = block_row + wm + mi * 16 + g;
        int row_hi = row_lo + 8;
        float s_lo = 1.f, s_hi = 1.f;
        if (SCALE) {
            s_lo = (row_lo < M) ? dinv[row_lo] : 0.f;
            s_hi = (row_hi < M) ? dinv[row_hi] : 0.f;
        }
#pragma unroll
        for (int na = 0; na < 4; na++) {
            int col = wn + na * 8 + 2 * tg;
            if (row_lo < M) {
                __half2 h = __floats2half2_rn(acc[mi][na][0] * s_lo, acc[mi][na][1] * s_lo);
                *reinterpret_cast<__half2*>(&C[(size_t)row_lo * 64 + col]) = h;
            }
            if (row_hi < M) {
                __half2 h = __floats2half2_rn(acc[mi][na][2] * s_hi, acc[mi][na][3] * s_hi);
                *reinterpret_cast<__half2*>(&C[(size_t)row_hi * 64 + col]) = h;
            }
        }
    }
}

// ---------------------------------------------------------------------------
// Gather-reduce (fp16 table, padded CSR)
// ---------------------------------------------------------------------------
__device__ __forceinline__ void acc_half4(float4& acc, uint2 u) {
    __half2 h0 = *reinterpret_cast<const __half2*>(&u.x);
    __half2 h1 = *reinterpret_cast<const __half2*>(&u.y);
    float2 f0 = __half22float2(h0);
    float2 f1 = __half22float2(h1);
    acc.x += f0.x; acc.y += f0.y; acc.z += f1.x; acc.w += f1.y;
}

template <bool RELU>
__global__ void gather_kernel(const uint2* __restrict__ hs, const int* __restrict__ cnt,
                              const int* __restrict__ srcs, const float* __restrict__ dinv,
                              const float* __restrict__ bias,
                              const int* __restrict__ nspill, const int* __restrict__ spill_d,
                              const int* __restrict__ spill_s,
                              float4* __restrict__ out, int N) {
    int i = blockIdx.x * blockDim.x + threadIdx.x;
    if (i >= N * 16) return;
    int node = i >> 4;
    int lane = i & 15;

    float4 acc = make_float4(0.f, 0.f, 0.f, 0.f);
    acc_half4(acc, hs[(size_t)node * 16 + lane]);  // self-loop term
    const int c = cnt[node];
    int e = node * CAP;
    const int end = e + min(c, CAP);

    for (; e + 4 <= end; e += 4) {
        int s0 = srcs[e], s1 = srcs[e + 1], s2 = srcs[e + 2], s3 = srcs[e + 3];
        uint2 v0 = hs[(size_t)s0 * 16 + lane];
        uint2 v1 = hs[(size_t)s1 * 16 + lane];
        uint2 v2 = hs[(size_t)s2 * 16 + lane];
        uint2 v3 = hs[(size_t)s3 * 16 + lane];
        acc_half4(acc, v0); acc_half4(acc, v1);
        acc_half4(acc, v2); acc_half4(acc, v3);
    }
    for (; e < end; e++) acc_half4(acc, hs[(size_t)srcs[e] * 16 + lane]);

    if (c > CAP) {  // overflow fixup (empty in practice)
        int ns = min(*nspill, MAX_SPILL);
        for (int j = 0; j < ns; j++)
            if (spill_d[j] == node) acc_half4(acc, hs[(size_t)spill_s[j] * 16 + lane]);
    }

    float dd = dinv[node];
    float4 bv = reinterpret_cast<const float4*>(bias)[lane];
    float r0 = fmaf(acc.x, dd, bv.x);
    float r1 = fmaf(acc.y, dd, bv.y);
    float r2 = fmaf(acc.z, dd, bv.z);
    float r3 = fmaf(acc.w, dd, bv.w);
    if (RELU) {
        r0 = fmaxf(r0, 0.f); r1 = fmaxf(r1, 0.f);
        r2 = fmaxf(r2, 0.f); r3 = fmaxf(r3, 0.f);
    }
    out[(size_t)node * 16 + lane] = make_float4(r0, r1, r2, r3);
}

// ---------------------------------------------------------------------------
// launch: graph fork — CSR build (side stream) overlaps GEMM1 raw (main)
// ---------------------------------------------------------------------------
extern "C" void kernel_launch(void* const* d_in, const int* in_sizes, int n_in,
                              void* d_out, int out_size) {
    const float* x = (const float*)d_in[0];
    const int* edge_index = (const int*)d_in[1];
    const float* W1 = (const float*)d_in[2];
    const float* b1 = (const float*)d_in[3];
    const float* W2 = (const float*)d_in[4];
    const float* b2 = (const float*)d_in[5];
    float* out = (float*)d_out;

    const int IN_CH = 256;
    const int N = in_sizes[0] / IN_CH;  // 100000
    const int E = in_sizes[1] / 2;      // 3200000
    const int* src = edge_index;
    const int* dst = edge_index + E;

    int *cnt, *srcs, *nspill, *spill_d, *spill_s;
    float *dinv, *hid;
    __half *h1, *h2;
    cudaGetSymbolAddress((void**)&cnt, g_cnt);
    cudaGetSymbolAddress((void**)&srcs, g_srcs);
    cudaGetSymbolAddress((void**)&nspill, g_nspill);
    cudaGetSymbolAddress((void**)&spill_d, g_spill_d);
    cudaGetSymbolAddress((void**)&spill_s, g_spill_s);
    cudaGetSymbolAddress((void**)&dinv, g_dinv);
    cudaGetSymbolAddress((void**)&h1, g_h1);
    cudaGetSymbolAddress((void**)&hid, g_hid);
    cudaGetSymbolAddress((void**)&h2, g_h2);

    static cudaStream_t s_side = nullptr;
    static cudaEvent_t evA = nullptr, evB = nullptr;
    if (s_side == nullptr) {
        cudaFuncSetAttribute((const void*)gemm_tf32_kernel<256, false>,
                             cudaFuncAttributeMaxDynamicSharedMemorySize, GEMM_SMEM_BYTES);
        cudaFuncSetAttribute((const void*)gemm_tf32_kernel<64, true>,
                             cudaFuncAttributeMaxDynamicSharedMemorySize, GEMM_SMEM_BYTES);
        cudaStreamCreateWithFlags(&s_side, cudaStreamNonBlocking);
        cudaEventCreateWithFlags(&evA, cudaEventDisableTiming);
        cudaEventCreateWithFlags(&evB, cudaEventDisableTiming);
    }

    const int T = 256;
    int nBlkN = (N + T - 1) / T;
    int nBlkE = (E + T - 1) / T;
    int nBlkG = (N + 127) / 128;
    int nBlkGa = (N * 16 + T - 1) / T;

    // main stream: zero counters, then fork
    zero_cnt_kernel<<<nBlkN, T>>>(cnt, nspill, N);
    cudaEventRecord(evA, 0);

    // side branch: CSR build + dinv
    cudaStreamWaitEvent(s_side, evA, 0);
    hist_scatter_kernel<<<nBlkE, T, 0, s_side>>>(src, dst, cnt, srcs,
                                                 nspill, spill_d, spill_s, E);
    dinv_kernel<<<nBlkN, T, 0, s_side>>>(cnt, dinv, N);
    cudaEventRecord(evB, s_side);

    // main branch: GEMM1 raw (no dinv dependency) — overlaps with side
    gemm_tf32_kernel<256, false><<<nBlkG, T, GEMM_SMEM_BYTES>>>(x, W1, dinv, h1, N);

    // join, then scale h1 by dinv in place
    cudaStreamWaitEvent(0, evB, 0);
    scale_h1_kernel<<<nBlkGa, T>>>((uint2*)h1, dinv, N);

    // layer 1 aggregation (+b1, relu) -> hid fp32
    gather_kernel<true><<<nBlkGa, T>>>((const uint2*)h1, cnt, srcs, dinv, b1,
                                       nspill, spill_d, spill_s, (float4*)hid, N);

    // layer 2 GEMM (scaled) -> h2 fp16
    gemm_tf32_kernel<64, true><<<nBlkG, T, GEMM_SMEM_BYTES>>>(hid, W2, dinv, h2, N);

    // final aggregation (+b2) -> fp32 out
    gather_kernel<false><<<nBlkGa, T>>>((const uint2*)h2, cnt, srcs, dinv, b2,
                                        nspill, spill_d, spill_s, (float4*)out, N);
}